// round 9
// baseline (speedup 1.0000x reference)
#include <cuda_runtime.h>
#include <cuda_bf16.h>
#include <cstdint>
#include <cstddef>

#define E_TOT 150000
#define TE    64          // rows per CTA tile
#define NT    256         // 8 warps
#define SA    136         // bf16 padded row stride (elements)
#define RB    272         // row bytes

// ---- smem layout (bytes) ----
#define OFF_VEC  0                       // 7 x 128 f32 = 3584
#define OFF_PART 3584                    // 2 x 64 float2 = 1024
#define OFF_A_HI 4608                    // 64*272 = 17408
#define OFF_A_LO (OFF_A_HI + 17408)
#define OFF_W    (OFF_A_LO + 17408)      // hi+lo contiguous: 69632
#define A_LO_B   17408
#define W_LO_B   34816
#define SMEM_SZ  (OFF_W + 69632)         // 109056 -> 2 CTAs/SM

// pre-split weights: 27 matrices, padded layout identical to smem
__device__ __align__(16) __nv_bfloat16 g_wsplit[27][2][128 * SA];
// pre-split x: linear [row][col]
__device__ __align__(16) __nv_bfloat16 g_xhi[(size_t)E_TOT * 128];
__device__ __align__(16) __nv_bfloat16 g_xlo[(size_t)E_TOT * 128];

// ---------------------------------------------------------------------------
__device__ __forceinline__ void split2(float v, __nv_bfloat16& hi, __nv_bfloat16& lo) {
    __nv_bfloat16 h = __float2bfloat16(v);
    hi = h;
    lo = __float2bfloat16(v - __bfloat162float(h));
}
__device__ __forceinline__ uint32_t pk(float a, float b) {
    __nv_bfloat162 t = __floats2bfloat162_rn(a, b);
    return *(uint32_t*)&t;
}
__device__ __forceinline__ uint32_t s2u(const void* p) {
    uint32_t a;
    asm("{ .reg .u64 t; cvta.to.shared.u64 t, %1; cvt.u32.u64 %0, t; }" : "=r"(a) : "l"(p));
    return a;
}
__device__ __forceinline__ void cpa16(uint32_t saddr, const void* g) {
    asm volatile("cp.async.cg.shared.global [%0], [%1], 16;" :: "r"(saddr), "l"(g));
}
__device__ __forceinline__ void cpa_commit() { asm volatile("cp.async.commit_group;" ::: "memory"); }

__device__ __forceinline__ void mma16816(float d[4], const uint32_t a[4],
                                         uint32_t b0, uint32_t b1) {
    asm volatile(
        "mma.sync.aligned.m16n8k16.row.col.f32.bf16.bf16.f32 "
        "{%0,%1,%2,%3}, {%4,%5,%6,%7}, {%8,%9}, {%0,%1,%2,%3};\n"
        : "+f"(d[0]), "+f"(d[1]), "+f"(d[2]), "+f"(d[3])
        : "r"(a[0]), "r"(a[1]), "r"(a[2]), "r"(a[3]), "r"(b0), "r"(b1));
}
#define LDSM4(r, addr) \
    asm volatile("ldmatrix.sync.aligned.m8n8.x4.shared.b16 {%0,%1,%2,%3}, [%4];" \
        : "=r"((r)[0]), "=r"((r)[1]), "=r"((r)[2]), "=r"((r)[3]) : "r"(addr))

__device__ __forceinline__ float tanhf_fast(float x) {
    float r; asm("tanh.approx.f32 %0, %1;" : "=f"(r) : "f"(x)); return r;
}
__device__ __forceinline__ float silu(float y) {
    return y * fmaf(0.5f, tanhf_fast(0.5f * y), 0.5f);
}

// ---------------------------------------------------------------------------
// prep (single kernel): blocks [0,27) split weights; blocks [27,...) split x
// ---------------------------------------------------------------------------
__global__ void prep_all(const float* __restrict__ x,
                         const float* __restrict__ W1,
                         const float* __restrict__ ef2w, const float* __restrict__ f2w,
                         const float* __restrict__ ef3w, const float* __restrict__ f3w) {
    if (blockIdx.x < 27) {
        int m = blockIdx.x;
        const float* src;
        if (m < 9)       src = W1 + (size_t)m * 16384;
        else if (m < 18) { int b = m - 9;  src = b ? f2w + (size_t)(b - 1) * 16384 : ef2w; }
        else             { int b = m - 18; src = b ? f3w + (size_t)(b - 1) * 16384 : ef3w; }
        __nv_bfloat16* hi = g_wsplit[m][0];
        __nv_bfloat16* lo = g_wsplit[m][1];
        for (int i = threadIdx.x; i < 16384; i += 256) {
            int r = i >> 7, c = i & 127;
            float v = __ldg(src + i);
            split2(v, hi[r * SA + c], lo[r * SA + c]);
        }
        return;
    }
    size_t i = (size_t)(blockIdx.x - 27) * 256 + threadIdx.x;  // one float4 per thread
    if (i >= (size_t)E_TOT * 32) return;
    float4 v = __ldg((const float4*)x + i);
    __nv_bfloat16 h0, l0, h1, l1, h2, l2, h3, l3;
    split2(v.x, h0, l0); split2(v.y, h1, l1);
    split2(v.z, h2, l2); split2(v.w, h3, l3);
    uint2 uh, ul;
    uh.x = pk(__bfloat162float(h0), __bfloat162float(h1));
    uh.y = pk(__bfloat162float(h2), __bfloat162float(h3));
    ul.x = pk(__bfloat162float(l0), __bfloat162float(l1));
    ul.y = pk(__bfloat162float(l2), __bfloat162float(l3));
    *(uint2*)(g_xhi + i * 4) = uh;
    *(uint2*)(g_xlo + i * 4) = ul;
}

// ---------------------------------------------------------------------------
// 64x128x128 GEMM from smem via ldmatrix, a-fragment software pipelined.
// Warp w: m-block (w>>1)*16, n-half (w&1). 1x8 m16n8 tiles, 3-product split.
// ---------------------------------------------------------------------------
__device__ __forceinline__ void gemm64(uint32_t sb, float acc[8][4], int warp, int lane) {
#pragma unroll
    for (int ni = 0; ni < 8; ni++)
#pragma unroll
        for (int j = 0; j < 4; j++) acc[ni][j] = 0.f;

    const int mblk = (warp >> 1) << 4;
    const int nblk = (warp & 1) << 6;

    const int rs_a = (lane & 7) + (((lane >> 3) & 1) << 3);
    const uint32_t ka = (lane >> 4) << 4;
    const uint32_t aaddr = sb + OFF_A_HI + (mblk + rs_a) * RB + ka;
    const int rs_b = (lane & 7) + ((lane >> 4) << 3);
    const uint32_t kb = ((lane >> 3) & 1) << 4;
    const uint32_t baddr = sb + OFF_W + (nblk + rs_b) * RB + kb;

    uint32_t ah[4], al[4], ahn[4], aln[4];
    LDSM4(ah, aaddr);
    LDSM4(al, aaddr + A_LO_B);

#pragma unroll 1
    for (int ks = 0; ks < 8; ks++) {
        const uint32_t k0b = ks << 5;
        if (ks < 7) {                       // prefetch next a fragments
            LDSM4(ahn, aaddr + k0b + 32);
            LDSM4(aln, aaddr + A_LO_B + k0b + 32);
        }
#pragma unroll
        for (int p = 0; p < 4; p++) {
            uint32_t bh[4], bl[4];
            const uint32_t bo = baddr + p * (16 * RB) + k0b;
            LDSM4(bh, bo);
            LDSM4(bl, bo + W_LO_B);
            mma16816(acc[2 * p],     ah, bh[0], bh[1]);
            mma16816(acc[2 * p],     ah, bl[0], bl[1]);
            mma16816(acc[2 * p],     al, bh[0], bh[1]);
            mma16816(acc[2 * p + 1], ah, bh[2], bh[3]);
            mma16816(acc[2 * p + 1], ah, bl[2], bl[3]);
            mma16816(acc[2 * p + 1], al, bh[2], bh[3]);
        }
#pragma unroll
        for (int j = 0; j < 4; j++) { ah[j] = ahn[j]; al[j] = aln[j]; }
    }
}

// ---------------------------------------------------------------------------
// epilogue part 1: bias add + row-sum/sumsq in registers, store partials.
// NO access to A/W smem — safe to run before the stage barrier.
// ---------------------------------------------------------------------------
__device__ __forceinline__ void epi_sums(char* sm, float acc[8][4], int vecb,
                                         int warp, int lane) {
    const int tig   = lane & 3;
    const int grp   = lane >> 2;
    const int nhalf = warp & 1;
    const int nblk  = nhalf << 6;
    const int r0    = ((warp >> 1) << 4) + grp;
    const float* bias = (const float*)(sm + OFF_VEC) + vecb * 128;

    float s0 = 0.f, q0 = 0.f, s1 = 0.f, q1 = 0.f;
#pragma unroll
    for (int ni = 0; ni < 8; ni++) {
        const int c = nblk + (ni << 3) + (tig << 1);
        const float b0 = bias[c], b1 = bias[c + 1];
        acc[ni][0] += b0; acc[ni][1] += b1;
        acc[ni][2] += b0; acc[ni][3] += b1;
        s0 += acc[ni][0] + acc[ni][1];
        q0 = fmaf(acc[ni][0], acc[ni][0], fmaf(acc[ni][1], acc[ni][1], q0));
        s1 += acc[ni][2] + acc[ni][3];
        q1 = fmaf(acc[ni][2], acc[ni][2], fmaf(acc[ni][3], acc[ni][3], q1));
    }
#pragma unroll
    for (int off = 1; off <= 2; off <<= 1) {
        s0 += __shfl_xor_sync(0xFFFFFFFFu, s0, off);
        q0 += __shfl_xor_sync(0xFFFFFFFFu, q0, off);
        s1 += __shfl_xor_sync(0xFFFFFFFFu, s1, off);
        q1 += __shfl_xor_sync(0xFFFFFFFFu, q1, off);
    }
    float2* part = (float2*)(sm + OFF_PART);
    if (tig == 0) {
        part[nhalf * 64 + r0]     = make_float2(s0, q0);
        part[nhalf * 64 + r0 + 8] = make_float2(s1, q1);
    }
}

// ---------------------------------------------------------------------------
// epilogue part 2 (after barrier): finish LN stats, SiLU, write A hi/lo.
// ---------------------------------------------------------------------------
__device__ __forceinline__ void epi_norm(char* sm, float acc[8][4], int vecb,
                                         int warp, int lane) {
    const int tig   = lane & 3;
    const int grp   = lane >> 2;
    const int nhalf = warp & 1;
    const int nblk  = nhalf << 6;
    const int r0    = ((warp >> 1) << 4) + grp;

    const float* vec = (const float*)(sm + OFF_VEC);
    const float* lw  = vec + vecb * 128 + 128;
    const float* lb  = lw + 128;

    const float2* part = (const float2*)(sm + OFF_PART);
    // re-derive own partials from partner side + own registers? Simpler:
    // read both halves (own half was stored pre-barrier)
    float2 own0 = part[nhalf * 64 + r0];
    float2 own1 = part[nhalf * 64 + r0 + 8];
    float2 o0   = part[(1 - nhalf) * 64 + r0];
    float2 o1   = part[(1 - nhalf) * 64 + r0 + 8];
    const float s0 = own0.x + o0.x, q0 = own0.y + o0.y;
    const float s1 = own1.x + o1.x, q1 = own1.y + o1.y;
    const float m0 = s0 * (1.0f / 128.0f);
    const float m1 = s1 * (1.0f / 128.0f);
    const float i0 = rsqrtf(fmaf(-m0, m0, q0 * (1.0f / 128.0f)) + 1e-5f);
    const float i1 = rsqrtf(fmaf(-m1, m1, q1 * (1.0f / 128.0f)) + 1e-5f);

#pragma unroll
    for (int ni = 0; ni < 8; ni++) {
        const int c = nblk + (ni << 3) + (tig << 1);
        const float w0 = lw[c], w1 = lw[c + 1], c0 = lb[c], c1 = lb[c + 1];
        float y00 = silu((acc[ni][0] - m0) * i0 * w0 + c0);
        float y01 = silu((acc[ni][1] - m0) * i0 * w1 + c1);
        float y10 = silu((acc[ni][2] - m1) * i1 * w0 + c0);
        float y11 = silu((acc[ni][3] - m1) * i1 * w1 + c1);
        __nv_bfloat16 h, l, h2, l2;
        const int o0b = r0 * RB + c * 2;
        const int o1b = (r0 + 8) * RB + c * 2;
        split2(y00, h, l); split2(y01, h2, l2);
        *(uint32_t*)(sm + OFF_A_HI + o0b) = pk(__bfloat162float(h), __bfloat162float(h2));
        *(uint32_t*)(sm + OFF_A_LO + o0b) = pk(__bfloat162float(l), __bfloat162float(l2));
        split2(y10, h, l); split2(y11, h2, l2);
        *(uint32_t*)(sm + OFF_A_HI + o1b) = pk(__bfloat162float(h), __bfloat162float(h2));
        *(uint32_t*)(sm + OFF_A_LO + o1b) = pk(__bfloat162float(l), __bfloat162float(l2));
    }
}

__device__ __forceinline__ void cp_weights(uint32_t sdst, int m, int tid) {
    const char* g = (const char*)g_wsplit[m];          // hi+lo contiguous 69632B
    for (int i = tid; i < 69632 / 16; i += NT)
        cpa16(sdst + i * 16, g + (size_t)i * 16);
    cpa_commit();
}

// ---------------------------------------------------------------------------
extern __shared__ char smraw[];

__global__ void __launch_bounds__(NT, 2)
urmlp_kernel(const float* __restrict__ b1c,
             const float* __restrict__ eln1w, const float* __restrict__ eln1b,
             const float* __restrict__ ef2b,
             const float* __restrict__ eln2w, const float* __restrict__ eln2b,
             const float* __restrict__ ef3b,
             const float* __restrict__ ln1w,  const float* __restrict__ ln1b,
             const float* __restrict__ f2b,
             const float* __restrict__ ln2w,  const float* __restrict__ ln2b,
             const float* __restrict__ f3b,
             float* __restrict__ out)
{
    char* sm = smraw;
    const int tid  = threadIdx.x;
    const int warp = tid >> 5;
    const int lane = tid & 31;
    const int bid  = blockIdx.x;
    const int tile = bid / 9;
    const int br   = bid - tile * 9;
    const int base = tile * TE;
    const int nvalid = min(TE, E_TOT - base);
    const uint32_t sb = s2u(sm);

    // g1: W1 -> W buf
    cp_weights(sb + OFF_W, br, tid);

    // g2: x tile hi/lo -> A; zero-fill invalid rows
    {
        for (int i = tid; i < TE * 16; i += NT) {
            const int row = i >> 4, ch = i & 15;
            const uint32_t dh = sb + OFF_A_HI + row * RB + ch * 16;
            if (row < nvalid) {
                const size_t go = (size_t)(base + row) * 128 + ch * 8;
                cpa16(dh, g_xhi + go);
                cpa16(dh + A_LO_B, g_xlo + go);
            } else {
                *(uint4*)(sm + OFF_A_HI + row * RB + ch * 16) = make_uint4(0, 0, 0, 0);
                *(uint4*)(sm + OFF_A_LO + row * RB + ch * 16) = make_uint4(0, 0, 0, 0);
            }
        }
        cpa_commit();
    }

    // per-branch vectors: [b1, lw1, lb1, b2, lw2, lb2, b3]
    if (tid < 128) {
        float* vec = (float*)(sm + OFF_VEC);
        const float* s0 = b1c + br * 128;
        const float* s1 = br ? ln1w + (br - 1) * 128 : eln1w;
        const float* s2 = br ? ln1b + (br - 1) * 128 : eln1b;
        const float* s3 = br ? f2b  + (br - 1) * 128 : ef2b;
        const float* s4 = br ? ln2w + (br - 1) * 128 : eln2w;
        const float* s5 = br ? ln2b + (br - 1) * 128 : eln2b;
        const float* s6 = br ? f3b  + (br - 1) * 128 : ef3b;
        vec[0 * 128 + tid] = __ldg(s0 + tid);
        vec[1 * 128 + tid] = __ldg(s1 + tid);
        vec[2 * 128 + tid] = __ldg(s2 + tid);
        vec[3 * 128 + tid] = __ldg(s3 + tid);
        vec[4 * 128 + tid] = __ldg(s4 + tid);
        vec[5 * 128 + tid] = __ldg(s5 + tid);
        vec[6 * 128 + tid] = __ldg(s6 + tid);
    }

    asm volatile("cp.async.wait_group 0;" ::: "memory");
    __syncthreads();

    float acc[8][4];

    // ---- stage 1 ----
    gemm64(sb, acc, warp, lane);
    epi_sums(sm, acc, 0, warp, lane);   // registers + partial store only
    __syncthreads();                    // gemm reads done + partials visible
    cp_weights(sb + OFF_W, 9 + br, tid);   // W2 (overlaps epi_norm)
    epi_norm(sm, acc, 0, warp, lane);
    asm volatile("cp.async.wait_group 0;" ::: "memory");
    __syncthreads();

    // ---- stage 2 ----
    gemm64(sb, acc, warp, lane);
    epi_sums(sm, acc, 3, warp, lane);
    __syncthreads();
    cp_weights(sb + OFF_W, 18 + br, tid);  // W3
    epi_norm(sm, acc, 3, warp, lane);
    asm volatile("cp.async.wait_group 0;" ::: "memory");
    __syncthreads();

    // ---- stage 3: out = h @ fc3^T + b3 ----
    gemm64(sb, acc, warp, lane);
    {
        const int grp  = lane >> 2;
        const int tig  = lane & 3;
        const int nblk = (warp & 1) << 6;
        const int r0   = ((warp >> 1) << 4) + grp;
        const float* bias = (const float*)(sm + OFF_VEC) + 6 * 128;
        float* o0 = out + ((size_t)br * E_TOT + base + r0) * 128;
        float* o1 = o0 + (size_t)8 * 128;
#pragma unroll
        for (int ni = 0; ni < 8; ni++) {
            const int c = nblk + (ni << 3) + (tig << 1);
            const float b0 = bias[c], b1 = bias[c + 1];
            if (r0 < nvalid)
                *(float2*)(o0 + c) = make_float2(acc[ni][0] + b0, acc[ni][1] + b1);
            if (r0 + 8 < nvalid)
                *(float2*)(o1 + c) = make_float2(acc[ni][2] + b0, acc[ni][3] + b1);
        }
    }
}

extern "C" void kernel_launch(void* const* d_in, const int* in_sizes, int n_in,
                              void* d_out, int out_size) {
    const float* x     = (const float*)d_in[0];
    const float* W1    = (const float*)d_in[1];
    const float* b1    = (const float*)d_in[2];
    const float* eln1w = (const float*)d_in[3];
    const float* eln1b = (const float*)d_in[4];
    const float* ef2w  = (const float*)d_in[5];
    const float* ef2b  = (const float*)d_in[6];
    const float* eln2w = (const float*)d_in[7];
    const float* eln2b = (const float*)d_in[8];
    const float* ef3w  = (const float*)d_in[9];
    const float* ef3b  = (const float*)d_in[10];
    const float* ln1w  = (const float*)d_in[11];
    const float* ln1b  = (const float*)d_in[12];
    const float* f2w   = (const float*)d_in[13];
    const float* f2b   = (const float*)d_in[14];
    const float* ln2w  = (const float*)d_in[15];
    const float* ln2b  = (const float*)d_in[16];
    const float* f3w   = (const float*)d_in[17];
    const float* f3b   = (const float*)d_in[18];
    float* out = (float*)d_out;

    cudaFuncSetAttribute(urmlp_kernel, cudaFuncAttributeMaxDynamicSharedMemorySize, SMEM_SZ);

    const int xblocks = (E_TOT * 32 + 255) / 256;
    prep_all<<<27 + xblocks, 256>>>(x, W1, ef2w, f2w, ef3w, f3w);

    const int tiles = (E_TOT + TE - 1) / TE;   // 2344
    urmlp_kernel<<<tiles * 9, NT, SMEM_SZ>>>(
        b1, eln1w, eln1b, ef2b, eln2w, eln2b, ef3b,
        ln1w, ln1b, f2b, ln2w, ln2b, f3b, out);
}

// round 10
// speedup vs baseline: 1.5827x; 1.5827x over previous
#include <cuda_runtime.h>
#include <cuda_bf16.h>
#include <cstdint>
#include <cstddef>

#define E_TOT 150000
#define TE    64          // rows per CTA tile
#define NT    256         // 8 warps
#define SA    136         // bf16 padded row stride (elements)
#define RB    272         // row bytes

// ---- smem layout (bytes) ----
#define OFF_VEC  0                       // 7 x 128 f32 = 3584
#define OFF_PART 3584                    // 4 x 64 float2 = 2048
#define OFF_A_HI 5632                    // 64*272 = 17408
#define OFF_A_LO (OFF_A_HI + 17408)
#define OFF_W    (OFF_A_LO + 17408)      // hi+lo contiguous: 69632
#define A_LO_B   17408
#define W_LO_B   34816
#define SMEM_SZ  (OFF_W + 69632)         // 110080 -> 2 CTAs/SM

// pre-split weights: 27 matrices, padded layout identical to smem
__device__ __align__(16) __nv_bfloat16 g_wsplit[27][2][128 * SA];
// pre-split x: linear [row][col]
__device__ __align__(16) __nv_bfloat16 g_xhi[(size_t)E_TOT * 128];
__device__ __align__(16) __nv_bfloat16 g_xlo[(size_t)E_TOT * 128];

// ---------------------------------------------------------------------------
__device__ __forceinline__ void split2(float v, __nv_bfloat16& hi, __nv_bfloat16& lo) {
    __nv_bfloat16 h = __float2bfloat16(v);
    hi = h;
    lo = __float2bfloat16(v - __bfloat162float(h));
}
__device__ __forceinline__ uint32_t pk(float a, float b) {
    __nv_bfloat162 t = __floats2bfloat162_rn(a, b);
    return *(uint32_t*)&t;
}
__device__ __forceinline__ uint32_t s2u(const void* p) {
    uint32_t a;
    asm("{ .reg .u64 t; cvta.to.shared.u64 t, %1; cvt.u32.u64 %0, t; }" : "=r"(a) : "l"(p));
    return a;
}
__device__ __forceinline__ void cpa16(uint32_t saddr, const void* g) {
    asm volatile("cp.async.cg.shared.global [%0], [%1], 16;" :: "r"(saddr), "l"(g));
}
__device__ __forceinline__ void cpa_commit() { asm volatile("cp.async.commit_group;" ::: "memory"); }

__device__ __forceinline__ void mma16816(float d[4], const uint32_t a[4],
                                         uint32_t b0, uint32_t b1) {
    asm volatile(
        "mma.sync.aligned.m16n8k16.row.col.f32.bf16.bf16.f32 "
        "{%0,%1,%2,%3}, {%4,%5,%6,%7}, {%8,%9}, {%0,%1,%2,%3};\n"
        : "+f"(d[0]), "+f"(d[1]), "+f"(d[2]), "+f"(d[3])
        : "r"(a[0]), "r"(a[1]), "r"(a[2]), "r"(a[3]), "r"(b0), "r"(b1));
}
#define LDSM4(r, addr) \
    asm volatile("ldmatrix.sync.aligned.m8n8.x4.shared.b16 {%0,%1,%2,%3}, [%4];" \
        : "=r"((r)[0]), "=r"((r)[1]), "=r"((r)[2]), "=r"((r)[3]) : "r"(addr))

__device__ __forceinline__ float tanhf_fast(float x) {
    float r; asm("tanh.approx.f32 %0, %1;" : "=f"(r) : "f"(x)); return r;
}
__device__ __forceinline__ float silu(float y) {
    return y * fmaf(0.5f, tanhf_fast(0.5f * y), 0.5f);
}

// ---------------------------------------------------------------------------
// prep (single kernel): blocks [0,27) split weights; blocks [27,...) split x
// ---------------------------------------------------------------------------
__global__ void prep_all(const float* __restrict__ x,
                         const float* __restrict__ W1,
                         const float* __restrict__ ef2w, const float* __restrict__ f2w,
                         const float* __restrict__ ef3w, const float* __restrict__ f3w) {
    if (blockIdx.x < 27) {
        int m = blockIdx.x;
        const float* src;
        if (m < 9)       src = W1 + (size_t)m * 16384;
        else if (m < 18) { int b = m - 9;  src = b ? f2w + (size_t)(b - 1) * 16384 : ef2w; }
        else             { int b = m - 18; src = b ? f3w + (size_t)(b - 1) * 16384 : ef3w; }
        __nv_bfloat16* hi = g_wsplit[m][0];
        __nv_bfloat16* lo = g_wsplit[m][1];
        for (int i = threadIdx.x; i < 16384; i += 256) {
            int r = i >> 7, c = i & 127;
            float v = __ldg(src + i);
            split2(v, hi[r * SA + c], lo[r * SA + c]);
        }
        return;
    }
    size_t i = (size_t)(blockIdx.x - 27) * 256 + threadIdx.x;  // one float4 per thread
    if (i >= (size_t)E_TOT * 32) return;
    float4 v = __ldg((const float4*)x + i);
    __nv_bfloat16 h0, l0, h1, l1, h2, l2, h3, l3;
    split2(v.x, h0, l0); split2(v.y, h1, l1);
    split2(v.z, h2, l2); split2(v.w, h3, l3);
    uint2 uh, ul;
    uh.x = pk(__bfloat162float(h0), __bfloat162float(h1));
    uh.y = pk(__bfloat162float(h2), __bfloat162float(h3));
    ul.x = pk(__bfloat162float(l0), __bfloat162float(l1));
    ul.y = pk(__bfloat162float(l2), __bfloat162float(l3));
    *(uint2*)(g_xhi + i * 4) = uh;
    *(uint2*)(g_xlo + i * 4) = ul;
}

// ---------------------------------------------------------------------------
// 64x128x128 GEMM from smem via ldmatrix, m32n32 warp tiles:
// 8 warps = 2 m-groups (warp>>2) x 4 n-groups (warp&3).
// Per k-step: 4 a-LDSM.x4 + 4 b-LDSM.x4 feed 24 HMMA (3-product split).
// acc[mi][nj][4]: mi = m16 block within m32, nj = n8 tile within n32.
// ---------------------------------------------------------------------------
__device__ __forceinline__ void gemm64(uint32_t sb, float acc[2][4][4], int warp, int lane) {
#pragma unroll
    for (int mi = 0; mi < 2; mi++)
#pragma unroll
        for (int nj = 0; nj < 4; nj++)
#pragma unroll
            for (int j = 0; j < 4; j++) acc[mi][nj][j] = 0.f;

    const int mblk = (warp >> 2) << 5;
    const int nblk = (warp & 3) << 5;

    const int rs_a = (lane & 7) + (((lane >> 3) & 1) << 3);
    const uint32_t ka = (lane >> 4) << 4;
    const uint32_t a0 = sb + OFF_A_HI + (mblk + rs_a) * RB + ka;   // m16 block 0
    const uint32_t a1 = a0 + 16 * RB;                              // m16 block 1
    const int rs_b = (lane & 7) + ((lane >> 4) << 3);
    const uint32_t kb = ((lane >> 3) & 1) << 4;
    const uint32_t b0 = sb + OFF_W + (nblk + rs_b) * RB + kb;      // n16 group 0
    const uint32_t b1 = b0 + 16 * RB;                              // n16 group 1

#pragma unroll 1
    for (int ks = 0; ks < 8; ks++) {
        const uint32_t k0b = ks << 5;                              // 16 elems = 32B
        uint32_t ah0[4], al0[4], ah1[4], al1[4];
        uint32_t bh0[4], bl0[4], bh1[4], bl1[4];
        LDSM4(ah0, a0 + k0b);
        LDSM4(al0, a0 + A_LO_B + k0b);
        LDSM4(ah1, a1 + k0b);
        LDSM4(al1, a1 + A_LO_B + k0b);
        LDSM4(bh0, b0 + k0b);
        LDSM4(bl0, b0 + W_LO_B + k0b);
        LDSM4(bh1, b1 + k0b);
        LDSM4(bl1, b1 + W_LO_B + k0b);

        // m-block 0
        mma16816(acc[0][0], ah0, bh0[0], bh0[1]);
        mma16816(acc[0][0], ah0, bl0[0], bl0[1]);
        mma16816(acc[0][0], al0, bh0[0], bh0[1]);
        mma16816(acc[0][1], ah0, bh0[2], bh0[3]);
        mma16816(acc[0][1], ah0, bl0[2], bl0[3]);
        mma16816(acc[0][1], al0, bh0[2], bh0[3]);
        mma16816(acc[0][2], ah0, bh1[0], bh1[1]);
        mma16816(acc[0][2], ah0, bl1[0], bl1[1]);
        mma16816(acc[0][2], al0, bh1[0], bh1[1]);
        mma16816(acc[0][3], ah0, bh1[2], bh1[3]);
        mma16816(acc[0][3], ah0, bl1[2], bl1[3]);
        mma16816(acc[0][3], al0, bh1[2], bh1[3]);
        // m-block 1
        mma16816(acc[1][0], ah1, bh0[0], bh0[1]);
        mma16816(acc[1][0], ah1, bl0[0], bl0[1]);
        mma16816(acc[1][0], al1, bh0[0], bh0[1]);
        mma16816(acc[1][1], ah1, bh0[2], bh0[3]);
        mma16816(acc[1][1], ah1, bl0[2], bl0[3]);
        mma16816(acc[1][1], al1, bh0[2], bh0[3]);
        mma16816(acc[1][2], ah1, bh1[0], bh1[1]);
        mma16816(acc[1][2], ah1, bl1[0], bl1[1]);
        mma16816(acc[1][2], al1, bh1[0], bh1[1]);
        mma16816(acc[1][3], ah1, bh1[2], bh1[3]);
        mma16816(acc[1][3], ah1, bl1[2], bl1[3]);
        mma16816(acc[1][3], al1, bh1[2], bh1[3]);
    }
}

// ---------------------------------------------------------------------------
// LN+SiLU epilogue: bias add, row stats (quad-shfl + 4-ngroup partials),
// normalize, split-bf16 -> A buffers. Internal __syncthreads.
// Lane owns rows mblk+grp+{0,8,16,24}, cols nblk + nj*8 + tig*2.
// ---------------------------------------------------------------------------
__device__ __forceinline__ void epilogue_ln(char* sm, float acc[2][4][4], int vecb,
                                            int warp, int lane) {
    const int tig  = lane & 3;
    const int grp  = lane >> 2;
    const int ngrp = warp & 3;
    const int mblk = (warp >> 2) << 5;
    const int nblk = ngrp << 5;

    const float* vec  = (const float*)(sm + OFF_VEC);
    const float* bias = vec + vecb * 128;
    const float* lw   = bias + 128;
    const float* lb   = bias + 256;

    float s[4] = {0.f, 0.f, 0.f, 0.f};
    float q[4] = {0.f, 0.f, 0.f, 0.f};
#pragma unroll
    for (int mi = 0; mi < 2; mi++) {
#pragma unroll
        for (int nj = 0; nj < 4; nj++) {
            const int c = nblk + (nj << 3) + (tig << 1);
            const float b0 = bias[c], b1 = bias[c + 1];
            float* a = acc[mi][nj];
            a[0] += b0; a[1] += b1; a[2] += b0; a[3] += b1;
            s[2 * mi]     += a[0] + a[1];
            q[2 * mi]      = fmaf(a[0], a[0], fmaf(a[1], a[1], q[2 * mi]));
            s[2 * mi + 1] += a[2] + a[3];
            q[2 * mi + 1]  = fmaf(a[2], a[2], fmaf(a[3], a[3], q[2 * mi + 1]));
        }
    }
#pragma unroll
    for (int off = 1; off <= 2; off <<= 1) {
#pragma unroll
        for (int i = 0; i < 4; i++) {
            s[i] += __shfl_xor_sync(0xFFFFFFFFu, s[i], off);
            q[i] += __shfl_xor_sync(0xFFFFFFFFu, q[i], off);
        }
    }
    float2* part = (float2*)(sm + OFF_PART);
    if (tig == 0) {
        // row order matches s/q index: +0 (mi0 lo), +8 (mi0 hi), +16, +24
        part[ngrp * 64 + mblk + grp]      = make_float2(s[0], q[0]);
        part[ngrp * 64 + mblk + grp + 8]  = make_float2(s[1], q[1]);
        part[ngrp * 64 + mblk + grp + 16] = make_float2(s[2], q[2]);
        part[ngrp * 64 + mblk + grp + 24] = make_float2(s[3], q[3]);
    }
    __syncthreads();
    float m[4], inv[4];
#pragma unroll
    for (int i = 0; i < 4; i++) {
        const int row = mblk + grp + (i << 3);
        float ss = 0.f, qq = 0.f;
#pragma unroll
        for (int ng = 0; ng < 4; ng++) {
            float2 p = part[ng * 64 + row];
            ss += p.x; qq += p.y;
        }
        m[i]   = ss * (1.0f / 128.0f);
        inv[i] = rsqrtf(fmaf(-m[i], m[i], qq * (1.0f / 128.0f)) + 1e-5f);
    }

#pragma unroll
    for (int mi = 0; mi < 2; mi++) {
        const int i0 = 2 * mi, i1 = 2 * mi + 1;
        const int r0 = mblk + grp + (mi << 4);
        const int r1 = r0 + 8;
#pragma unroll
        for (int nj = 0; nj < 4; nj++) {
            const int c = nblk + (nj << 3) + (tig << 1);
            const float w0 = lw[c], w1 = lw[c + 1], c0 = lb[c], c1 = lb[c + 1];
            const float* a = acc[mi][nj];
            float y00 = silu((a[0] - m[i0]) * inv[i0] * w0 + c0);
            float y01 = silu((a[1] - m[i0]) * inv[i0] * w1 + c1);
            float y10 = silu((a[2] - m[i1]) * inv[i1] * w0 + c0);
            float y11 = silu((a[3] - m[i1]) * inv[i1] * w1 + c1);
            __nv_bfloat16 h, l, h2, l2;
            const int o0b = r0 * RB + c * 2;
            const int o1b = r1 * RB + c * 2;
            split2(y00, h, l); split2(y01, h2, l2);
            *(uint32_t*)(sm + OFF_A_HI + o0b) = pk(__bfloat162float(h), __bfloat162float(h2));
            *(uint32_t*)(sm + OFF_A_LO + o0b) = pk(__bfloat162float(l), __bfloat162float(l2));
            split2(y10, h, l); split2(y11, h2, l2);
            *(uint32_t*)(sm + OFF_A_HI + o1b) = pk(__bfloat162float(h), __bfloat162float(h2));
            *(uint32_t*)(sm + OFF_A_LO + o1b) = pk(__bfloat162float(l), __bfloat162float(l2));
        }
    }
}

__device__ __forceinline__ void cp_weights(uint32_t sdst, int m, int tid) {
    const char* g = (const char*)g_wsplit[m];          // hi+lo contiguous 69632B
    for (int i = tid; i < 69632 / 16; i += NT)
        cpa16(sdst + i * 16, g + (size_t)i * 16);
    cpa_commit();
}

// ---------------------------------------------------------------------------
extern __shared__ char smraw[];

__global__ void __launch_bounds__(NT, 2)
urmlp_kernel(const float* __restrict__ b1c,
             const float* __restrict__ eln1w, const float* __restrict__ eln1b,
             const float* __restrict__ ef2b,
             const float* __restrict__ eln2w, const float* __restrict__ eln2b,
             const float* __restrict__ ef3b,
             const float* __restrict__ ln1w,  const float* __restrict__ ln1b,
             const float* __restrict__ f2b,
             const float* __restrict__ ln2w,  const float* __restrict__ ln2b,
             const float* __restrict__ f3b,
             float* __restrict__ out)
{
    char* sm = smraw;
    const int tid  = threadIdx.x;
    const int warp = tid >> 5;
    const int lane = tid & 31;
    const int bid  = blockIdx.x;
    const int tile = bid / 9;
    const int br   = bid - tile * 9;
    const int base = tile * TE;
    const int nvalid = min(TE, E_TOT - base);
    const uint32_t sb = s2u(sm);

    // g1: W1 -> W buf
    cp_weights(sb + OFF_W, br, tid);

    // g2: x tile hi/lo -> A; zero-fill invalid rows
    {
        for (int i = tid; i < TE * 16; i += NT) {       // 16 x 16B chunks per row
            const int row = i >> 4, ch = i & 15;
            const uint32_t dh = sb + OFF_A_HI + row * RB + ch * 16;
            if (row < nvalid) {
                const size_t go = (size_t)(base + row) * 128 + ch * 8;
                cpa16(dh, g_xhi + go);
                cpa16(dh + A_LO_B, g_xlo + go);
            } else {
                *(uint4*)(sm + OFF_A_HI + row * RB + ch * 16) = make_uint4(0, 0, 0, 0);
                *(uint4*)(sm + OFF_A_LO + row * RB + ch * 16) = make_uint4(0, 0, 0, 0);
            }
        }
        cpa_commit();
    }

    // per-branch vectors: [b1, lw1, lb1, b2, lw2, lb2, b3]
    if (tid < 128) {
        float* vec = (float*)(sm + OFF_VEC);
        const float* s0 = b1c + br * 128;
        const float* s1 = br ? ln1w + (br - 1) * 128 : eln1w;
        const float* s2 = br ? ln1b + (br - 1) * 128 : eln1b;
        const float* s3 = br ? f2b  + (br - 1) * 128 : ef2b;
        const float* s4 = br ? ln2w + (br - 1) * 128 : eln2w;
        const float* s5 = br ? ln2b + (br - 1) * 128 : eln2b;
        const float* s6 = br ? f3b  + (br - 1) * 128 : ef3b;
        vec[0 * 128 + tid] = __ldg(s0 + tid);
        vec[1 * 128 + tid] = __ldg(s1 + tid);
        vec[2 * 128 + tid] = __ldg(s2 + tid);
        vec[3 * 128 + tid] = __ldg(s3 + tid);
        vec[4 * 128 + tid] = __ldg(s4 + tid);
        vec[5 * 128 + tid] = __ldg(s5 + tid);
        vec[6 * 128 + tid] = __ldg(s6 + tid);
    }

    asm volatile("cp.async.wait_group 0;" ::: "memory");
    __syncthreads();

    float acc[2][4][4];

    // ---- stage 1 ----
    gemm64(sb, acc, warp, lane);
    __syncthreads();                    // all reads of a/w done
    cp_weights(sb + OFF_W, 9 + br, tid);   // W2, overlaps epilogue
    epilogue_ln(sm, acc, 0, warp, lane);
    asm volatile("cp.async.wait_group 0;" ::: "memory");
    __syncthreads();

    // ---- stage 2 ----
    gemm64(sb, acc, warp, lane);
    __syncthreads();
    cp_weights(sb + OFF_W, 18 + br, tid);  // W3
    epilogue_ln(sm, acc, 3, warp, lane);
    asm volatile("cp.async.wait_group 0;" ::: "memory");
    __syncthreads();

    // ---- stage 3: out = h @ fc3^T + b3 ----
    gemm64(sb, acc, warp, lane);
    {
        const int tig  = lane & 3;
        const int grp  = lane >> 2;
        const int mblk = (warp >> 2) << 5;
        const int nblk = (warp & 3) << 5;
        const float* bias = (const float*)(sm + OFF_VEC) + 6 * 128;
#pragma unroll
        for (int mi = 0; mi < 2; mi++) {
            const int r0 = mblk + grp + (mi << 4);
            const int r1 = r0 + 8;
            float* o0 = out + ((size_t)br * E_TOT + base + r0) * 128;
            float* o1 = o0 + (size_t)8 * 128;
#pragma unroll
            for (int nj = 0; nj < 4; nj++) {
                const int c = nblk + (nj << 3) + (tig << 1);
                const float b0 = bias[c], b1 = bias[c + 1];
                const float* a = acc[mi][nj];
                if (r0 < nvalid)
                    *(float2*)(o0 + c) = make_float2(a[0] + b0, a[1] + b1);
                if (r1 < nvalid)
                    *(float2*)(o1 + c) = make_float2(a[2] + b0, a[3] + b1);
            }
        }
    }
}

extern "C" void kernel_launch(void* const* d_in, const int* in_sizes, int n_in,
                              void* d_out, int out_size) {
    const float* x     = (const float*)d_in[0];
    const float* W1    = (const float*)d_in[1];
    const float* b1    = (const float*)d_in[2];
    const float* eln1w = (const float*)d_in[3];
    const float* eln1b = (const float*)d_in[4];
    const float* ef2w  = (const float*)d_in[5];
    const float* ef2b  = (const float*)d_in[6];
    const float* eln2w = (const float*)d_in[7];
    const float* eln2b = (const float*)d_in[8];
    const float* ef3w  = (const float*)d_in[9];
    const float* ef3b  = (const float*)d_in[10];
    const float* ln1w  = (const float*)d_in[11];
    const float* ln1b  = (const float*)d_in[12];
    const float* f2w   = (const float*)d_in[13];
    const float* f2b   = (const float*)d_in[14];
    const float* ln2w  = (const float*)d_in[15];
    const float* ln2b  = (const float*)d_in[16];
    const float* f3w   = (const float*)d_in[17];
    const float* f3b   = (const float*)d_in[18];
    float* out = (float*)d_out;

    cudaFuncSetAttribute(urmlp_kernel, cudaFuncAttributeMaxDynamicSharedMemorySize, SMEM_SZ);

    const int xblocks = (E_TOT * 32 + 255) / 256;
    prep_all<<<27 + xblocks, 256>>>(x, W1, ef2w, f2w, ef3w, f3w);

    const int tiles = (E_TOT + TE - 1) / TE;   // 2344
    urmlp_kernel<<<tiles * 9, NT, SMEM_SZ>>>(
        b1, eln1w, eln1b, ef2b, eln2w, eln2b, ef3b,
        ln1w, ln1b, f2b, ln2w, ln2b, f3b, out);
}

// round 11
// speedup vs baseline: 2.2255x; 1.4061x over previous
#include <cuda_runtime.h>
#include <cuda_fp16.h>
#include <cstdint>
#include <cstddef>

#define E_TOT 150000
#define TE    64          // rows per CTA tile
#define NT    256         // 8 warps
#define SA    136         // fp16 padded row stride (elements)
#define RB    272         // row bytes

// ---- smem layout (bytes) ----
#define OFF_VEC  0                       // 7 x 128 f32 = 3584
#define OFF_PART 3584                    // 4 x 64 float2 = 2048
#define OFF_A_HI 5632                    // 64*272 = 17408
#define OFF_A_LO (OFF_A_HI + 17408)
#define OFF_W    (OFF_A_LO + 17408)      // single fp16: 128*272 = 34816
#define A_LO_B   17408
#define SMEM_SZ  (OFF_W + 34816)         // 75264 -> 3 CTAs/SM

// pre-rounded weights: 27 matrices, fp16, padded layout identical to smem
__device__ __align__(16) __half g_w[27][128 * SA];
// pre-split x: fp16 hi/lo, linear [row][col]
__device__ __align__(16) __half g_xhi[(size_t)E_TOT * 128];
__device__ __align__(16) __half g_xlo[(size_t)E_TOT * 128];

// ---------------------------------------------------------------------------
__device__ __forceinline__ void split2h(float v, __half& hi, __half& lo) {
    __half h = __float2half_rn(v);
    hi = h;
    lo = __float2half_rn(v - __half2float(h));
}
__device__ __forceinline__ uint32_t pkh(float a, float b) {
    __half2 t = __floats2half2_rn(a, b);
    return *(uint32_t*)&t;
}
__device__ __forceinline__ uint32_t s2u(const void* p) {
    uint32_t a;
    asm("{ .reg .u64 t; cvta.to.shared.u64 t, %1; cvt.u32.u64 %0, t; }" : "=r"(a) : "l"(p));
    return a;
}
__device__ __forceinline__ void cpa16(uint32_t saddr, const void* g) {
    asm volatile("cp.async.cg.shared.global [%0], [%1], 16;" :: "r"(saddr), "l"(g));
}
__device__ __forceinline__ void cpa_commit() { asm volatile("cp.async.commit_group;" ::: "memory"); }

__device__ __forceinline__ void mma16816(float d[4], const uint32_t a[4],
                                         uint32_t b0, uint32_t b1) {
    asm volatile(
        "mma.sync.aligned.m16n8k16.row.col.f32.f16.f16.f32 "
        "{%0,%1,%2,%3}, {%4,%5,%6,%7}, {%8,%9}, {%0,%1,%2,%3};\n"
        : "+f"(d[0]), "+f"(d[1]), "+f"(d[2]), "+f"(d[3])
        : "r"(a[0]), "r"(a[1]), "r"(a[2]), "r"(a[3]), "r"(b0), "r"(b1));
}
#define LDSM4(r, addr) \
    asm volatile("ldmatrix.sync.aligned.m8n8.x4.shared.b16 {%0,%1,%2,%3}, [%4];" \
        : "=r"((r)[0]), "=r"((r)[1]), "=r"((r)[2]), "=r"((r)[3]) : "r"(addr))

__device__ __forceinline__ float tanhf_fast(float x) {
    float r; asm("tanh.approx.f32 %0, %1;" : "=f"(r) : "f"(x)); return r;
}
__device__ __forceinline__ float silu(float y) {
    return y * fmaf(0.5f, tanhf_fast(0.5f * y), 0.5f);
}

// ---------------------------------------------------------------------------
// prep (single kernel): blocks [0,27) round weights; blocks [27,...) split x
// ---------------------------------------------------------------------------
__global__ void prep_all(const float* __restrict__ x,
                         const float* __restrict__ W1,
                         const float* __restrict__ ef2w, const float* __restrict__ f2w,
                         const float* __restrict__ ef3w, const float* __restrict__ f3w) {
    if (blockIdx.x < 27) {
        int m = blockIdx.x;
        const float* src;
        if (m < 9)       src = W1 + (size_t)m * 16384;
        else if (m < 18) { int b = m - 9;  src = b ? f2w + (size_t)(b - 1) * 16384 : ef2w; }
        else             { int b = m - 18; src = b ? f3w + (size_t)(b - 1) * 16384 : ef3w; }
        __half* w = g_w[m];
        for (int i = threadIdx.x; i < 16384; i += 256) {
            int r = i >> 7, c = i & 127;
            w[r * SA + c] = __float2half_rn(__ldg(src + i));
        }
        return;
    }
    size_t i = (size_t)(blockIdx.x - 27) * 256 + threadIdx.x;  // one float4 per thread
    if (i >= (size_t)E_TOT * 32) return;
    float4 v = __ldg((const float4*)x + i);
    __half h0, l0, h1, l1, h2, l2, h3, l3;
    split2h(v.x, h0, l0); split2h(v.y, h1, l1);
    split2h(v.z, h2, l2); split2h(v.w, h3, l3);
    uint2 uh, ul;
    uh.x = pkh(__half2float(h0), __half2float(h1));
    uh.y = pkh(__half2float(h2), __half2float(h3));
    ul.x = pkh(__half2float(l0), __half2float(l1));
    ul.y = pkh(__half2float(l2), __half2float(l3));
    *(uint2*)(g_xhi + i * 4) = uh;
    *(uint2*)(g_xlo + i * 4) = ul;
}

// ---------------------------------------------------------------------------
// 64x128x128 GEMM from smem via ldmatrix, m32n32 warp tiles:
// 8 warps = 2 m-groups (warp>>2) x 4 n-groups (warp&3).
// Per k-step: 4 a-LDSM.x4 + 2 b-LDSM.x4 feed 16 HMMA (2-product fp16 split).
// acc[mi][nj][4]: mi = m16 block within m32, nj = n8 tile within n32.
// ---------------------------------------------------------------------------
__device__ __forceinline__ void gemm64(uint32_t sb, float acc[2][4][4], int warp, int lane) {
#pragma unroll
    for (int mi = 0; mi < 2; mi++)
#pragma unroll
        for (int nj = 0; nj < 4; nj++)
#pragma unroll
            for (int j = 0; j < 4; j++) acc[mi][nj][j] = 0.f;

    const int mblk = (warp >> 2) << 5;
    const int nblk = (warp & 3) << 5;

    const int rs_a = (lane & 7) + (((lane >> 3) & 1) << 3);
    const uint32_t ka = (lane >> 4) << 4;
    const uint32_t a0 = sb + OFF_A_HI + (mblk + rs_a) * RB + ka;   // m16 block 0
    const uint32_t a1 = a0 + 16 * RB;                              // m16 block 1
    const int rs_b = (lane & 7) + ((lane >> 4) << 3);
    const uint32_t kb = ((lane >> 3) & 1) << 4;
    const uint32_t b0 = sb + OFF_W + (nblk + rs_b) * RB + kb;      // n16 group 0
    const uint32_t b1 = b0 + 16 * RB;                              // n16 group 1

#pragma unroll 1
    for (int ks = 0; ks < 8; ks++) {
        const uint32_t k0b = ks << 5;                              // 16 elems = 32B
        uint32_t ah0[4], al0[4], ah1[4], al1[4];
        uint32_t bh0[4], bh1[4];
        LDSM4(ah0, a0 + k0b);
        LDSM4(al0, a0 + A_LO_B + k0b);
        LDSM4(ah1, a1 + k0b);
        LDSM4(al1, a1 + A_LO_B + k0b);
        LDSM4(bh0, b0 + k0b);
        LDSM4(bh1, b1 + k0b);

        // m-block 0
        mma16816(acc[0][0], ah0, bh0[0], bh0[1]);
        mma16816(acc[0][0], al0, bh0[0], bh0[1]);
        mma16816(acc[0][1], ah0, bh0[2], bh0[3]);
        mma16816(acc[0][1], al0, bh0[2], bh0[3]);
        mma16816(acc[0][2], ah0, bh1[0], bh1[1]);
        mma16816(acc[0][2], al0, bh1[0], bh1[1]);
        mma16816(acc[0][3], ah0, bh1[2], bh1[3]);
        mma16816(acc[0][3], al0, bh1[2], bh1[3]);
        // m-block 1
        mma16816(acc[1][0], ah1, bh0[0], bh0[1]);
        mma16816(acc[1][0], al1, bh0[0], bh0[1]);
        mma16816(acc[1][1], ah1, bh0[2], bh0[3]);
        mma16816(acc[1][1], al1, bh0[2], bh0[3]);
        mma16816(acc[1][2], ah1, bh1[0], bh1[1]);
        mma16816(acc[1][2], al1, bh1[0], bh1[1]);
        mma16816(acc[1][3], ah1, bh1[2], bh1[3]);
        mma16816(acc[1][3], al1, bh1[2], bh1[3]);
    }
}

// ---------------------------------------------------------------------------
// LN+SiLU epilogue: bias add, row stats (quad-shfl + 4-ngroup partials),
// normalize, fp16-split -> A buffers. Internal __syncthreads.
// ---------------------------------------------------------------------------
__device__ __forceinline__ void epilogue_ln(char* sm, float acc[2][4][4], int vecb,
                                            int warp, int lane) {
    const int tig  = lane & 3;
    const int grp  = lane >> 2;
    const int ngrp = warp & 3;
    const int mblk = (warp >> 2) << 5;
    const int nblk = ngrp << 5;

    const float* vec  = (const float*)(sm + OFF_VEC);
    const float* bias = vec + vecb * 128;
    const float* lw   = bias + 128;
    const float* lb   = bias + 256;

    float s[4] = {0.f, 0.f, 0.f, 0.f};
    float q[4] = {0.f, 0.f, 0.f, 0.f};
#pragma unroll
    for (int mi = 0; mi < 2; mi++) {
#pragma unroll
        for (int nj = 0; nj < 4; nj++) {
            const int c = nblk + (nj << 3) + (tig << 1);
            const float b0 = bias[c], b1 = bias[c + 1];
            float* a = acc[mi][nj];
            a[0] += b0; a[1] += b1; a[2] += b0; a[3] += b1;
            s[2 * mi]     += a[0] + a[1];
            q[2 * mi]      = fmaf(a[0], a[0], fmaf(a[1], a[1], q[2 * mi]));
            s[2 * mi + 1] += a[2] + a[3];
            q[2 * mi + 1]  = fmaf(a[2], a[2], fmaf(a[3], a[3], q[2 * mi + 1]));
        }
    }
#pragma unroll
    for (int off = 1; off <= 2; off <<= 1) {
#pragma unroll
        for (int i = 0; i < 4; i++) {
            s[i] += __shfl_xor_sync(0xFFFFFFFFu, s[i], off);
            q[i] += __shfl_xor_sync(0xFFFFFFFFu, q[i], off);
        }
    }
    float2* part = (float2*)(sm + OFF_PART);
    if (tig == 0) {
        part[ngrp * 64 + mblk + grp]      = make_float2(s[0], q[0]);
        part[ngrp * 64 + mblk + grp + 8]  = make_float2(s[1], q[1]);
        part[ngrp * 64 + mblk + grp + 16] = make_float2(s[2], q[2]);
        part[ngrp * 64 + mblk + grp + 24] = make_float2(s[3], q[3]);
    }
    __syncthreads();
    float m[4], inv[4];
#pragma unroll
    for (int i = 0; i < 4; i++) {
        const int row = mblk + grp + (i << 3);
        float ss = 0.f, qq = 0.f;
#pragma unroll
        for (int ng = 0; ng < 4; ng++) {
            float2 p = part[ng * 64 + row];
            ss += p.x; qq += p.y;
        }
        m[i]   = ss * (1.0f / 128.0f);
        inv[i] = rsqrtf(fmaf(-m[i], m[i], qq * (1.0f / 128.0f)) + 1e-5f);
    }

#pragma unroll
    for (int mi = 0; mi < 2; mi++) {
        const int i0 = 2 * mi, i1 = 2 * mi + 1;
        const int r0 = mblk + grp + (mi << 4);
        const int r1 = r0 + 8;
#pragma unroll
        for (int nj = 0; nj < 4; nj++) {
            const int c = nblk + (nj << 3) + (tig << 1);
            const float w0 = lw[c], w1 = lw[c + 1], c0 = lb[c], c1 = lb[c + 1];
            const float* a = acc[mi][nj];
            float y00 = silu((a[0] - m[i0]) * inv[i0] * w0 + c0);
            float y01 = silu((a[1] - m[i0]) * inv[i0] * w1 + c1);
            float y10 = silu((a[2] - m[i1]) * inv[i1] * w0 + c0);
            float y11 = silu((a[3] - m[i1]) * inv[i1] * w1 + c1);
            __half h, l, h2, l2;
            const int o0b = r0 * RB + c * 2;
            const int o1b = r1 * RB + c * 2;
            split2h(y00, h, l); split2h(y01, h2, l2);
            *(uint32_t*)(sm + OFF_A_HI + o0b) = pkh(__half2float(h), __half2float(h2));
            *(uint32_t*)(sm + OFF_A_LO + o0b) = pkh(__half2float(l), __half2float(l2));
            split2h(y10, h, l); split2h(y11, h2, l2);
            *(uint32_t*)(sm + OFF_A_HI + o1b) = pkh(__half2float(h), __half2float(h2));
            *(uint32_t*)(sm + OFF_A_LO + o1b) = pkh(__half2float(l), __half2float(l2));
        }
    }
}

__device__ __forceinline__ void cp_weights(uint32_t sdst, int m, int tid) {
    const char* g = (const char*)g_w[m];               // 34816B fp16
    for (int i = tid; i < 34816 / 16; i += NT)
        cpa16(sdst + i * 16, g + (size_t)i * 16);
    cpa_commit();
}

// ---------------------------------------------------------------------------
extern __shared__ char smraw[];

__global__ void __launch_bounds__(NT, 3)
urmlp_kernel(const float* __restrict__ b1c,
             const float* __restrict__ eln1w, const float* __restrict__ eln1b,
             const float* __restrict__ ef2b,
             const float* __restrict__ eln2w, const float* __restrict__ eln2b,
             const float* __restrict__ ef3b,
             const float* __restrict__ ln1w,  const float* __restrict__ ln1b,
             const float* __restrict__ f2b,
             const float* __restrict__ ln2w,  const float* __restrict__ ln2b,
             const float* __restrict__ f3b,
             float* __restrict__ out)
{
    char* sm = smraw;
    const int tid  = threadIdx.x;
    const int warp = tid >> 5;
    const int lane = tid & 31;
    const int bid  = blockIdx.x;
    const int tile = bid / 9;
    const int br   = bid - tile * 9;
    const int base = tile * TE;
    const int nvalid = min(TE, E_TOT - base);
    const uint32_t sb = s2u(sm);

    // g1: W1 -> W buf
    cp_weights(sb + OFF_W, br, tid);

    // g2: x tile hi/lo -> A; zero-fill invalid rows
    {
        for (int i = tid; i < TE * 16; i += NT) {       // 16 x 16B chunks per row
            const int row = i >> 4, ch = i & 15;
            const uint32_t dh = sb + OFF_A_HI + row * RB + ch * 16;
            if (row < nvalid) {
                const size_t go = (size_t)(base + row) * 128 + ch * 8;
                cpa16(dh, g_xhi + go);
                cpa16(dh + A_LO_B, g_xlo + go);
            } else {
                *(uint4*)(sm + OFF_A_HI + row * RB + ch * 16) = make_uint4(0, 0, 0, 0);
                *(uint4*)(sm + OFF_A_LO + row * RB + ch * 16) = make_uint4(0, 0, 0, 0);
            }
        }
        cpa_commit();
    }

    // per-branch vectors: [b1, lw1, lb1, b2, lw2, lb2, b3]
    if (tid < 128) {
        float* vec = (float*)(sm + OFF_VEC);
        const float* s0 = b1c + br * 128;
        const float* s1 = br ? ln1w + (br - 1) * 128 : eln1w;
        const float* s2 = br ? ln1b + (br - 1) * 128 : eln1b;
        const float* s3 = br ? f2b  + (br - 1) * 128 : ef2b;
        const float* s4 = br ? ln2w + (br - 1) * 128 : eln2w;
        const float* s5 = br ? ln2b + (br - 1) * 128 : eln2b;
        const float* s6 = br ? f3b  + (br - 1) * 128 : ef3b;
        vec[0 * 128 + tid] = __ldg(s0 + tid);
        vec[1 * 128 + tid] = __ldg(s1 + tid);
        vec[2 * 128 + tid] = __ldg(s2 + tid);
        vec[3 * 128 + tid] = __ldg(s3 + tid);
        vec[4 * 128 + tid] = __ldg(s4 + tid);
        vec[5 * 128 + tid] = __ldg(s5 + tid);
        vec[6 * 128 + tid] = __ldg(s6 + tid);
    }

    asm volatile("cp.async.wait_group 0;" ::: "memory");
    __syncthreads();

    float acc[2][4][4];

    // ---- stage 1 ----
    gemm64(sb, acc, warp, lane);
    __syncthreads();                    // all reads of a/w done
    cp_weights(sb + OFF_W, 9 + br, tid);   // W2, overlaps epilogue
    epilogue_ln(sm, acc, 0, warp, lane);
    asm volatile("cp.async.wait_group 0;" ::: "memory");
    __syncthreads();

    // ---- stage 2 ----
    gemm64(sb, acc, warp, lane);
    __syncthreads();
    cp_weights(sb + OFF_W, 18 + br, tid);  // W3
    epilogue_ln(sm, acc, 3, warp, lane);
    asm volatile("cp.async.wait_group 0;" ::: "memory");
    __syncthreads();

    // ---- stage 3: out = h @ fc3^T + b3 ----
    gemm64(sb, acc, warp, lane);
    {
        const int tig  = lane & 3;
        const int grp  = lane >> 2;
        const int mblk = (warp >> 2) << 5;
        const int nblk = (warp & 3) << 5;
        const float* bias = (const float*)(sm + OFF_VEC) + 6 * 128;
#pragma unroll
        for (int mi = 0; mi < 2; mi++) {
            const int r0 = mblk + grp + (mi << 4);
            const int r1 = r0 + 8;
            float* o0 = out + ((size_t)br * E_TOT + base + r0) * 128;
            float* o1 = o0 + (size_t)8 * 128;
#pragma unroll
            for (int nj = 0; nj < 4; nj++) {
                const int c = nblk + (nj << 3) + (tig << 1);
                const float b0 = bias[c], b1 = bias[c + 1];
                const float* a = acc[mi][nj];
                if (r0 < nvalid)
                    *(float2*)(o0 + c) = make_float2(a[0] + b0, a[1] + b1);
                if (r1 < nvalid)
                    *(float2*)(o1 + c) = make_float2(a[2] + b0, a[3] + b1);
            }
        }
    }
}

extern "C" void kernel_launch(void* const* d_in, const int* in_sizes, int n_in,
                              void* d_out, int out_size) {
    const float* x     = (const float*)d_in[0];
    const float* W1    = (const float*)d_in[1];
    const float* b1    = (const float*)d_in[2];
    const float* eln1w = (const float*)d_in[3];
    const float* eln1b = (const float*)d_in[4];
    const float* ef2w  = (const float*)d_in[5];
    const float* ef2b  = (const float*)d_in[6];
    const float* eln2w = (const float*)d_in[7];
    const float* eln2b = (const float*)d_in[8];
    const float* ef3w  = (const float*)d_in[9];
    const float* ef3b  = (const float*)d_in[10];
    const float* ln1w  = (const float*)d_in[11];
    const float* ln1b  = (const float*)d_in[12];
    const float* f2w   = (const float*)d_in[13];
    const float* f2b   = (const float*)d_in[14];
    const float* ln2w  = (const float*)d_in[15];
    const float* ln2b  = (const float*)d_in[16];
    const float* f3w   = (const float*)d_in[17];
    const float* f3b   = (const float*)d_in[18];
    float* out = (float*)d_out;

    cudaFuncSetAttribute(urmlp_kernel, cudaFuncAttributeMaxDynamicSharedMemorySize, SMEM_SZ);

    const int xblocks = (E_TOT * 32 + 255) / 256;
    prep_all<<<27 + xblocks, 256>>>(x, W1, ef2w, f2w, ef3w, f3w);

    const int tiles = (E_TOT + TE - 1) / TE;   // 2344
    urmlp_kernel<<<tiles * 9, NT, SMEM_SZ>>>(
        b1, eln1w, eln1b, ef2b, eln2w, eln2b, ef3b,
        ln1w, ln1b, f2b, ln2w, ln2b, f3b, out);
}

// round 12
// speedup vs baseline: 3.0827x; 1.3852x over previous
#include <cuda_runtime.h>
#include <cuda_fp16.h>
#include <cstdint>
#include <cstddef>

#define E_TOT 150000
#define TE    64          // rows per CTA tile
#define NT    256         // 8 warps
#define SA    136         // fp16 padded row stride (elements)
#define RB    272         // row bytes

// ---- smem layout (bytes) ----
#define OFF_VEC  0                       // 7 x 128 f32 = 3584
#define OFF_PART 3584                    // 4 x 64 float2 = 2048
#define OFF_A    5632                    // 64*272 = 17408
#define OFF_W    (OFF_A + 17408)         // single fp16: 128*272 = 34816
#define SMEM_SZ  (OFF_W + 34816)         // 57856 -> 3 CTAs/SM

// pre-rounded weights: 27 matrices, fp16, padded layout identical to smem
__device__ __align__(16) __half g_w[27][128 * SA];
// pre-rounded x: fp16, linear [row][col]
__device__ __align__(16) __half g_x[(size_t)E_TOT * 128];

// ---------------------------------------------------------------------------
__device__ __forceinline__ uint32_t pkh(float a, float b) {
    __half2 t = __floats2half2_rn(a, b);
    return *(uint32_t*)&t;
}
__device__ __forceinline__ uint32_t s2u(const void* p) {
    uint32_t a;
    asm("{ .reg .u64 t; cvta.to.shared.u64 t, %1; cvt.u32.u64 %0, t; }" : "=r"(a) : "l"(p));
    return a;
}
__device__ __forceinline__ void cpa16(uint32_t saddr, const void* g) {
    asm volatile("cp.async.cg.shared.global [%0], [%1], 16;" :: "r"(saddr), "l"(g));
}
__device__ __forceinline__ void cpa_commit() { asm volatile("cp.async.commit_group;" ::: "memory"); }

__device__ __forceinline__ void mma16816(float d[4], const uint32_t a[4],
                                         uint32_t b0, uint32_t b1) {
    asm volatile(
        "mma.sync.aligned.m16n8k16.row.col.f32.f16.f16.f32 "
        "{%0,%1,%2,%3}, {%4,%5,%6,%7}, {%8,%9}, {%0,%1,%2,%3};\n"
        : "+f"(d[0]), "+f"(d[1]), "+f"(d[2]), "+f"(d[3])
        : "r"(a[0]), "r"(a[1]), "r"(a[2]), "r"(a[3]), "r"(b0), "r"(b1));
}
#define LDSM4(r, addr) \
    asm volatile("ldmatrix.sync.aligned.m8n8.x4.shared.b16 {%0,%1,%2,%3}, [%4];" \
        : "=r"((r)[0]), "=r"((r)[1]), "=r"((r)[2]), "=r"((r)[3]) : "r"(addr))

__device__ __forceinline__ float tanhf_fast(float x) {
    float r; asm("tanh.approx.f32 %0, %1;" : "=f"(r) : "f"(x)); return r;
}
__device__ __forceinline__ float silu(float y) {
    return y * fmaf(0.5f, tanhf_fast(0.5f * y), 0.5f);
}

// ---------------------------------------------------------------------------
// prep (single kernel): blocks [0,27) round weights; blocks [27,...) round x
// ---------------------------------------------------------------------------
__global__ void prep_all(const float* __restrict__ x,
                         const float* __restrict__ W1,
                         const float* __restrict__ ef2w, const float* __restrict__ f2w,
                         const float* __restrict__ ef3w, const float* __restrict__ f3w) {
    if (blockIdx.x < 27) {
        int m = blockIdx.x;
        const float* src;
        if (m < 9)       src = W1 + (size_t)m * 16384;
        else if (m < 18) { int b = m - 9;  src = b ? f2w + (size_t)(b - 1) * 16384 : ef2w; }
        else             { int b = m - 18; src = b ? f3w + (size_t)(b - 1) * 16384 : ef3w; }
        __half* w = g_w[m];
        for (int i = threadIdx.x; i < 16384; i += 256) {
            int r = i >> 7, c = i & 127;
            w[r * SA + c] = __float2half_rn(__ldg(src + i));
        }
        return;
    }
    size_t i = (size_t)(blockIdx.x - 27) * 256 + threadIdx.x;  // one float4 per thread
    if (i >= (size_t)E_TOT * 32) return;
    float4 v = __ldg((const float4*)x + i);
    uint2 uh;
    uh.x = pkh(v.x, v.y);
    uh.y = pkh(v.z, v.w);
    *(uint2*)(g_x + i * 4) = uh;
}

// ---------------------------------------------------------------------------
// 64x128x128 GEMM from smem via ldmatrix, m32n32 warp tiles:
// 8 warps = 2 m-groups (warp>>2) x 4 n-groups (warp&3).
// Per k-step: 2 a-LDSM.x4 + 2 b-LDSM.x4 feed 8 HMMA (pure fp16).
// acc[mi][nj][4]: mi = m16 block within m32, nj = n8 tile within n32.
// ---------------------------------------------------------------------------
__device__ __forceinline__ void gemm64(uint32_t sb, float acc[2][4][4], int warp, int lane) {
#pragma unroll
    for (int mi = 0; mi < 2; mi++)
#pragma unroll
        for (int nj = 0; nj < 4; nj++)
#pragma unroll
            for (int j = 0; j < 4; j++) acc[mi][nj][j] = 0.f;

    const int mblk = (warp >> 2) << 5;
    const int nblk = (warp & 3) << 5;

    const int rs_a = (lane & 7) + (((lane >> 3) & 1) << 3);
    const uint32_t ka = (lane >> 4) << 4;
    const uint32_t a0 = sb + OFF_A + (mblk + rs_a) * RB + ka;      // m16 block 0
    const uint32_t a1 = a0 + 16 * RB;                              // m16 block 1
    const int rs_b = (lane & 7) + ((lane >> 4) << 3);
    const uint32_t kb = ((lane >> 3) & 1) << 4;
    const uint32_t b0 = sb + OFF_W + (nblk + rs_b) * RB + kb;      // n16 group 0
    const uint32_t b1 = b0 + 16 * RB;                              // n16 group 1

#pragma unroll 1
    for (int ks = 0; ks < 8; ks++) {
        const uint32_t k0b = ks << 5;                              // 16 elems = 32B
        uint32_t ah0[4], ah1[4];
        uint32_t bh0[4], bh1[4];
        LDSM4(ah0, a0 + k0b);
        LDSM4(ah1, a1 + k0b);
        LDSM4(bh0, b0 + k0b);
        LDSM4(bh1, b1 + k0b);

        mma16816(acc[0][0], ah0, bh0[0], bh0[1]);
        mma16816(acc[0][1], ah0, bh0[2], bh0[3]);
        mma16816(acc[0][2], ah0, bh1[0], bh1[1]);
        mma16816(acc[0][3], ah0, bh1[2], bh1[3]);
        mma16816(acc[1][0], ah1, bh0[0], bh0[1]);
        mma16816(acc[1][1], ah1, bh0[2], bh0[3]);
        mma16816(acc[1][2], ah1, bh1[0], bh1[1]);
        mma16816(acc[1][3], ah1, bh1[2], bh1[3]);
    }
}

// ---------------------------------------------------------------------------
// LN+SiLU epilogue: bias add, row stats (quad-shfl + 4-ngroup partials),
// normalize, fp16 -> A buffer. Internal __syncthreads.
// ---------------------------------------------------------------------------
__device__ __forceinline__ void epilogue_ln(char* sm, float acc[2][4][4], int vecb,
                                            int warp, int lane) {
    const int tig  = lane & 3;
    const int grp  = lane >> 2;
    const int ngrp = warp & 3;
    const int mblk = (warp >> 2) << 5;
    const int nblk = ngrp << 5;

    const float* vec  = (const float*)(sm + OFF_VEC);
    const float* bias = vec + vecb * 128;
    const float* lw   = bias + 128;
    const float* lb   = bias + 256;

    float s[4] = {0.f, 0.f, 0.f, 0.f};
    float q[4] = {0.f, 0.f, 0.f, 0.f};
#pragma unroll
    for (int mi = 0; mi < 2; mi++) {
#pragma unroll
        for (int nj = 0; nj < 4; nj++) {
            const int c = nblk + (nj << 3) + (tig << 1);
            const float b0 = bias[c], b1 = bias[c + 1];
            float* a = acc[mi][nj];
            a[0] += b0; a[1] += b1; a[2] += b0; a[3] += b1;
            s[2 * mi]     += a[0] + a[1];
            q[2 * mi]      = fmaf(a[0], a[0], fmaf(a[1], a[1], q[2 * mi]));
            s[2 * mi + 1] += a[2] + a[3];
            q[2 * mi + 1]  = fmaf(a[2], a[2], fmaf(a[3], a[3], q[2 * mi + 1]));
        }
    }
#pragma unroll
    for (int off = 1; off <= 2; off <<= 1) {
#pragma unroll
        for (int i = 0; i < 4; i++) {
            s[i] += __shfl_xor_sync(0xFFFFFFFFu, s[i], off);
            q[i] += __shfl_xor_sync(0xFFFFFFFFu, q[i], off);
        }
    }
    float2* part = (float2*)(sm + OFF_PART);
    if (tig == 0) {
        part[ngrp * 64 + mblk + grp]      = make_float2(s[0], q[0]);
        part[ngrp * 64 + mblk + grp + 8]  = make_float2(s[1], q[1]);
        part[ngrp * 64 + mblk + grp + 16] = make_float2(s[2], q[2]);
        part[ngrp * 64 + mblk + grp + 24] = make_float2(s[3], q[3]);
    }
    __syncthreads();
    float m[4], inv[4];
#pragma unroll
    for (int i = 0; i < 4; i++) {
        const int row = mblk + grp + (i << 3);
        float ss = 0.f, qq = 0.f;
#pragma unroll
        for (int ng = 0; ng < 4; ng++) {
            float2 p = part[ng * 64 + row];
            ss += p.x; qq += p.y;
        }
        m[i]   = ss * (1.0f / 128.0f);
        inv[i] = rsqrtf(fmaf(-m[i], m[i], qq * (1.0f / 128.0f)) + 1e-5f);
    }

#pragma unroll
    for (int mi = 0; mi < 2; mi++) {
        const int i0 = 2 * mi, i1 = 2 * mi + 1;
        const int r0 = mblk + grp + (mi << 4);
        const int r1 = r0 + 8;
#pragma unroll
        for (int nj = 0; nj < 4; nj++) {
            const int c = nblk + (nj << 3) + (tig << 1);
            const float w0 = lw[c], w1 = lw[c + 1], c0 = lb[c], c1 = lb[c + 1];
            const float* a = acc[mi][nj];
            float y00 = silu((a[0] - m[i0]) * inv[i0] * w0 + c0);
            float y01 = silu((a[1] - m[i0]) * inv[i0] * w1 + c1);
            float y10 = silu((a[2] - m[i1]) * inv[i1] * w0 + c0);
            float y11 = silu((a[3] - m[i1]) * inv[i1] * w1 + c1);
            *(uint32_t*)(sm + OFF_A + r0 * RB + c * 2) = pkh(y00, y01);
            *(uint32_t*)(sm + OFF_A + r1 * RB + c * 2) = pkh(y10, y11);
        }
    }
}

__device__ __forceinline__ void cp_weights(uint32_t sdst, int m, int tid) {
    const char* g = (const char*)g_w[m];               // 34816B fp16
    for (int i = tid; i < 34816 / 16; i += NT)
        cpa16(sdst + i * 16, g + (size_t)i * 16);
    cpa_commit();
}

// ---------------------------------------------------------------------------
extern __shared__ char smraw[];

__global__ void __launch_bounds__(NT, 3)
urmlp_kernel(const float* __restrict__ b1c,
             const float* __restrict__ eln1w, const float* __restrict__ eln1b,
             const float* __restrict__ ef2b,
             const float* __restrict__ eln2w, const float* __restrict__ eln2b,
             const float* __restrict__ ef3b,
             const float* __restrict__ ln1w,  const float* __restrict__ ln1b,
             const float* __restrict__ f2b,
             const float* __restrict__ ln2w,  const float* __restrict__ ln2b,
             const float* __restrict__ f3b,
             float* __restrict__ out)
{
    char* sm = smraw;
    const int tid  = threadIdx.x;
    const int warp = tid >> 5;
    const int lane = tid & 31;
    const int bid  = blockIdx.x;
    const int tile = bid / 9;
    const int br   = bid - tile * 9;
    const int base = tile * TE;
    const int nvalid = min(TE, E_TOT - base);
    const uint32_t sb = s2u(sm);

    // g1: W1 -> W buf
    cp_weights(sb + OFF_W, br, tid);

    // g2: x tile -> A; zero-fill invalid rows
    {
        for (int i = tid; i < TE * 16; i += NT) {       // 16 x 16B chunks per row
            const int row = i >> 4, ch = i & 15;
            const uint32_t dh = sb + OFF_A + row * RB + ch * 16;
            if (row < nvalid) {
                cpa16(dh, g_x + (size_t)(base + row) * 128 + ch * 8);
            } else {
                *(uint4*)(sm + OFF_A + row * RB + ch * 16) = make_uint4(0, 0, 0, 0);
            }
        }
        cpa_commit();
    }

    // per-branch vectors: [b1, lw1, lb1, b2, lw2, lb2, b3]
    if (tid < 128) {
        float* vec = (float*)(sm + OFF_VEC);
        const float* s0 = b1c + br * 128;
        const float* s1 = br ? ln1w + (br - 1) * 128 : eln1w;
        const float* s2 = br ? ln1b + (br - 1) * 128 : eln1b;
        const float* s3 = br ? f2b  + (br - 1) * 128 : ef2b;
        const float* s4 = br ? ln2w + (br - 1) * 128 : eln2w;
        const float* s5 = br ? ln2b + (br - 1) * 128 : eln2b;
        const float* s6 = br ? f3b  + (br - 1) * 128 : ef3b;
        vec[0 * 128 + tid] = __ldg(s0 + tid);
        vec[1 * 128 + tid] = __ldg(s1 + tid);
        vec[2 * 128 + tid] = __ldg(s2 + tid);
        vec[3 * 128 + tid] = __ldg(s3 + tid);
        vec[4 * 128 + tid] = __ldg(s4 + tid);
        vec[5 * 128 + tid] = __ldg(s5 + tid);
        vec[6 * 128 + tid] = __ldg(s6 + tid);
    }

    asm volatile("cp.async.wait_group 0;" ::: "memory");
    __syncthreads();

    float acc[2][4][4];

    // ---- stage 1 ----
    gemm64(sb, acc, warp, lane);
    __syncthreads();                    // all reads of a/w done
    cp_weights(sb + OFF_W, 9 + br, tid);   // W2, overlaps epilogue
    epilogue_ln(sm, acc, 0, warp, lane);
    asm volatile("cp.async.wait_group 0;" ::: "memory");
    __syncthreads();

    // ---- stage 2 ----
    gemm64(sb, acc, warp, lane);
    __syncthreads();
    cp_weights(sb + OFF_W, 18 + br, tid);  // W3
    epilogue_ln(sm, acc, 3, warp, lane);
    asm volatile("cp.async.wait_group 0;" ::: "memory");
    __syncthreads();

    // ---- stage 3: out = h @ fc3^T + b3 ----
    gemm64(sb, acc, warp, lane);
    {
        const int tig  = lane & 3;
        const int grp  = lane >> 2;
        const int mblk = (warp >> 2) << 5;
        const int nblk = (warp & 3) << 5;
        const float* bias = (const float*)(sm + OFF_VEC) + 6 * 128;
#pragma unroll
        for (int mi = 0; mi < 2; mi++) {
            const int r0 = mblk + grp + (mi << 4);
            const int r1 = r0 + 8;
            float* o0 = out + ((size_t)br * E_TOT + base + r0) * 128;
            float* o1 = o0 + (size_t)8 * 128;
#pragma unroll
            for (int nj = 0; nj < 4; nj++) {
                const int c = nblk + (nj << 3) + (tig << 1);
                const float b0 = bias[c], b1 = bias[c + 1];
                const float* a = acc[mi][nj];
                if (r0 < nvalid)
                    *(float2*)(o0 + c) = make_float2(a[0] + b0, a[1] + b1);
                if (r1 < nvalid)
                    *(float2*)(o1 + c) = make_float2(a[2] + b0, a[3] + b1);
            }
        }
    }
}

extern "C" void kernel_launch(void* const* d_in, const int* in_sizes, int n_in,
                              void* d_out, int out_size) {
    const float* x     = (const float*)d_in[0];
    const float* W1    = (const float*)d_in[1];
    const float* b1    = (const float*)d_in[2];
    const float* eln1w = (const float*)d_in[3];
    const float* eln1b = (const float*)d_in[4];
    const float* ef2w  = (const float*)d_in[5];
    const float* ef2b  = (const float*)d_in[6];
    const float* eln2w = (const float*)d_in[7];
    const float* eln2b = (const float*)d_in[8];
    const float* ef3w  = (const float*)d_in[9];
    const float* ef3b  = (const float*)d_in[10];
    const float* ln1w  = (const float*)d_in[11];
    const float* ln1b  = (const float*)d_in[12];
    const float* f2w   = (const float*)d_in[13];
    const float* f2b   = (const float*)d_in[14];
    const float* ln2w  = (const float*)d_in[15];
    const float* ln2b  = (const float*)d_in[16];
    const float* f3w   = (const float*)d_in[17];
    const float* f3b   = (const float*)d_in[18];
    float* out = (float*)d_out;

    cudaFuncSetAttribute(urmlp_kernel, cudaFuncAttributeMaxDynamicSharedMemorySize, SMEM_SZ);

    const int xblocks = (E_TOT * 32 + 255) / 256;
    prep_all<<<27 + xblocks, 256>>>(x, W1, ef2w, f2w, ef3w, f3w);

    const int tiles = (E_TOT + TE - 1) / TE;   // 2344
    urmlp_kernel<<<tiles * 9, NT, SMEM_SZ>>>(
        b1, eln1w, eln1b, ef2b, eln2w, eln2b, ef3b,
        ln1w, ln1b, f2b, ln2w, ln2b, f3b, out);
}

// round 13
// speedup vs baseline: 3.5395x; 1.1482x over previous
#include <cuda_runtime.h>
#include <cuda_fp16.h>
#include <cstdint>
#include <cstddef>

#define E_TOT 150000
#define TE    128         // rows per CTA tile
#define NT    256         // 8 warps = 4 m-groups x 2 n-groups
#define SA    136         // fp16 padded row stride (elements)
#define RB    272         // row bytes

// ---- smem layout (bytes) ----
#define OFF_VEC  0                       // 7 x 128 f32 = 3584
#define OFF_PART 3584                    // 2 x 128 float2 = 2048
#define OFF_A    5632                    // 128*272 = 34816
#define OFF_W    (OFF_A + 34816)         // single fp16: 128*272 = 34816
#define SMEM_SZ  (OFF_W + 34816)         // 75264 -> 2 CTAs/SM (reg-capped)

// pre-rounded weights: 27 matrices, fp16, padded layout identical to smem
__device__ __align__(16) __half g_w[27][128 * SA];
// pre-rounded x: fp16, linear [row][col]
__device__ __align__(16) __half g_x[(size_t)E_TOT * 128];

// ---------------------------------------------------------------------------
__device__ __forceinline__ uint32_t pkh(float a, float b) {
    __half2 t = __floats2half2_rn(a, b);
    return *(uint32_t*)&t;
}
__device__ __forceinline__ uint32_t s2u(const void* p) {
    uint32_t a;
    asm("{ .reg .u64 t; cvta.to.shared.u64 t, %1; cvt.u32.u64 %0, t; }" : "=r"(a) : "l"(p));
    return a;
}
__device__ __forceinline__ void cpa16(uint32_t saddr, const void* g) {
    asm volatile("cp.async.cg.shared.global [%0], [%1], 16;" :: "r"(saddr), "l"(g));
}
__device__ __forceinline__ void cpa_commit() { asm volatile("cp.async.commit_group;" ::: "memory"); }

__device__ __forceinline__ void mma16816(float d[4], const uint32_t a[4],
                                         uint32_t b0, uint32_t b1) {
    asm volatile(
        "mma.sync.aligned.m16n8k16.row.col.f32.f16.f16.f32 "
        "{%0,%1,%2,%3}, {%4,%5,%6,%7}, {%8,%9}, {%0,%1,%2,%3};\n"
        : "+f"(d[0]), "+f"(d[1]), "+f"(d[2]), "+f"(d[3])
        : "r"(a[0]), "r"(a[1]), "r"(a[2]), "r"(a[3]), "r"(b0), "r"(b1));
}
#define LDSM4(r, addr) \
    asm volatile("ldmatrix.sync.aligned.m8n8.x4.shared.b16 {%0,%1,%2,%3}, [%4];" \
        : "=r"((r)[0]), "=r"((r)[1]), "=r"((r)[2]), "=r"((r)[3]) : "r"(addr))

__device__ __forceinline__ float tanhf_fast(float x) {
    float r; asm("tanh.approx.f32 %0, %1;" : "=f"(r) : "f"(x)); return r;
}
__device__ __forceinline__ float silu(float y) {
    return y * fmaf(0.5f, tanhf_fast(0.5f * y), 0.5f);
}

// ---------------------------------------------------------------------------
// prep (single kernel): blocks [0,27) round weights; blocks [27,...) round x
// ---------------------------------------------------------------------------
__global__ void prep_all(const float* __restrict__ x,
                         const float* __restrict__ W1,
                         const float* __restrict__ ef2w, const float* __restrict__ f2w,
                         const float* __restrict__ ef3w, const float* __restrict__ f3w) {
    if (blockIdx.x < 27) {
        int m = blockIdx.x;
        const float* src;
        if (m < 9)       src = W1 + (size_t)m * 16384;
        else if (m < 18) { int b = m - 9;  src = b ? f2w + (size_t)(b - 1) * 16384 : ef2w; }
        else             { int b = m - 18; src = b ? f3w + (size_t)(b - 1) * 16384 : ef3w; }
        __half* w = g_w[m];
        for (int i = threadIdx.x; i < 16384; i += 256) {
            int r = i >> 7, c = i & 127;
            w[r * SA + c] = __float2half_rn(__ldg(src + i));
        }
        return;
    }
    size_t i = (size_t)(blockIdx.x - 27) * 256 + threadIdx.x;  // one float4 per thread
    if (i >= (size_t)E_TOT * 32) return;
    float4 v = __ldg((const float4*)x + i);
    uint2 uh;
    uh.x = pkh(v.x, v.y);
    uh.y = pkh(v.z, v.w);
    *(uint2*)(g_x + i * 4) = uh;
}

// ---------------------------------------------------------------------------
// 128x128x128 GEMM from smem via ldmatrix, m32n64 warp tiles:
// 8 warps = 4 m-groups (warp>>1) x 2 n-groups (warp&1).
// Per k-step: 2 a-LDSM.x4 + 4 b-LDSM.x4 feed 16 HMMA (1.5 wf/HMMA).
// acc[mi][nj][4]: mi = m16 block within m32, nj = n8 tile within n64.
// ---------------------------------------------------------------------------
__device__ __forceinline__ void gemm128(uint32_t sb, float acc[2][8][4], int warp, int lane) {
#pragma unroll
    for (int mi = 0; mi < 2; mi++)
#pragma unroll
        for (int nj = 0; nj < 8; nj++)
#pragma unroll
            for (int j = 0; j < 4; j++) acc[mi][nj][j] = 0.f;

    const int mblk = (warp >> 1) << 5;
    const int nblk = (warp & 1) << 6;

    const int rs_a = (lane & 7) + (((lane >> 3) & 1) << 3);
    const uint32_t ka = (lane >> 4) << 4;
    const uint32_t a0 = sb + OFF_A + (mblk + rs_a) * RB + ka;      // m16 block 0
    const uint32_t a1 = a0 + 16 * RB;                              // m16 block 1
    const int rs_b = (lane & 7) + ((lane >> 4) << 3);
    const uint32_t kb = ((lane >> 3) & 1) << 4;
    const uint32_t bb = sb + OFF_W + (nblk + rs_b) * RB + kb;      // n16 group base

#pragma unroll 1
    for (int ks = 0; ks < 8; ks++) {
        const uint32_t k0b = ks << 5;                              // 16 elems = 32B
        uint32_t ah0[4], ah1[4];
        uint32_t bf[4][4];
        LDSM4(ah0, a0 + k0b);
        LDSM4(ah1, a1 + k0b);
#pragma unroll
        for (int p = 0; p < 4; p++)
            LDSM4(bf[p], bb + p * (16 * RB) + k0b);

#pragma unroll
        for (int p = 0; p < 4; p++) {
            mma16816(acc[0][2 * p],     ah0, bf[p][0], bf[p][1]);
            mma16816(acc[0][2 * p + 1], ah0, bf[p][2], bf[p][3]);
            mma16816(acc[1][2 * p],     ah1, bf[p][0], bf[p][1]);
            mma16816(acc[1][2 * p + 1], ah1, bf[p][2], bf[p][3]);
        }
    }
}

// ---------------------------------------------------------------------------
// LN+SiLU epilogue: bias add, row stats (quad-shfl + 2-ngroup partials),
// normalize, fp16 -> A buffer. Internal __syncthreads.
// Lane owns rows mblk + grp + {0,8,16,24}; cols nblk + nj*8 + tig*2 (nj 0..7).
// ---------------------------------------------------------------------------
__device__ __forceinline__ void epilogue_ln(char* sm, float acc[2][8][4], int vecb,
                                            int warp, int lane) {
    const int tig  = lane & 3;
    const int grp  = lane >> 2;
    const int ngrp = warp & 1;
    const int mblk = (warp >> 1) << 5;
    const int nblk = ngrp << 6;

    const float* vec  = (const float*)(sm + OFF_VEC);
    const float* bias = vec + vecb * 128;
    const float* lw   = bias + 128;
    const float* lb   = bias + 256;

    float s[4] = {0.f, 0.f, 0.f, 0.f};
    float q[4] = {0.f, 0.f, 0.f, 0.f};
#pragma unroll
    for (int mi = 0; mi < 2; mi++) {
#pragma unroll
        for (int nj = 0; nj < 8; nj++) {
            const int c = nblk + (nj << 3) + (tig << 1);
            const float b0 = bias[c], b1 = bias[c + 1];
            float* a = acc[mi][nj];
            a[0] += b0; a[1] += b1; a[2] += b0; a[3] += b1;
            s[2 * mi]     += a[0] + a[1];
            q[2 * mi]      = fmaf(a[0], a[0], fmaf(a[1], a[1], q[2 * mi]));
            s[2 * mi + 1] += a[2] + a[3];
            q[2 * mi + 1]  = fmaf(a[2], a[2], fmaf(a[3], a[3], q[2 * mi + 1]));
        }
    }
#pragma unroll
    for (int off = 1; off <= 2; off <<= 1) {
#pragma unroll
        for (int i = 0; i < 4; i++) {
            s[i] += __shfl_xor_sync(0xFFFFFFFFu, s[i], off);
            q[i] += __shfl_xor_sync(0xFFFFFFFFu, q[i], off);
        }
    }
    float2* part = (float2*)(sm + OFF_PART);
    if (tig == 0) {
        part[ngrp * 128 + mblk + grp]      = make_float2(s[0], q[0]);
        part[ngrp * 128 + mblk + grp + 8]  = make_float2(s[1], q[1]);
        part[ngrp * 128 + mblk + grp + 16] = make_float2(s[2], q[2]);
        part[ngrp * 128 + mblk + grp + 24] = make_float2(s[3], q[3]);
    }
    __syncthreads();
    float m[4], inv[4];
#pragma unroll
    for (int i = 0; i < 4; i++) {
        const int row = mblk + grp + (i << 3);
        float2 p0 = part[row];
        float2 p1 = part[128 + row];
        const float ss = p0.x + p1.x, qq = p0.y + p1.y;
        m[i]   = ss * (1.0f / 128.0f);
        inv[i] = rsqrtf(fmaf(-m[i], m[i], qq * (1.0f / 128.0f)) + 1e-5f);
    }

#pragma unroll
    for (int mi = 0; mi < 2; mi++) {
        const int i0 = 2 * mi, i1 = 2 * mi + 1;
        const int r0 = mblk + grp + (mi << 4);
        const int r1 = r0 + 8;
#pragma unroll
        for (int nj = 0; nj < 8; nj++) {
            const int c = nblk + (nj << 3) + (tig << 1);
            const float w0 = lw[c], w1 = lw[c + 1], c0 = lb[c], c1 = lb[c + 1];
            const float* a = acc[mi][nj];
            float y00 = silu((a[0] - m[i0]) * inv[i0] * w0 + c0);
            float y01 = silu((a[1] - m[i0]) * inv[i0] * w1 + c1);
            float y10 = silu((a[2] - m[i1]) * inv[i1] * w0 + c0);
            float y11 = silu((a[3] - m[i1]) * inv[i1] * w1 + c1);
            *(uint32_t*)(sm + OFF_A + r0 * RB + c * 2) = pkh(y00, y01);
            *(uint32_t*)(sm + OFF_A + r1 * RB + c * 2) = pkh(y10, y11);
        }
    }
}

__device__ __forceinline__ void cp_weights(uint32_t sdst, int m, int tid) {
    const char* g = (const char*)g_w[m];               // 34816B fp16
    for (int i = tid; i < 34816 / 16; i += NT)
        cpa16(sdst + i * 16, g + (size_t)i * 16);
    cpa_commit();
}

// ---------------------------------------------------------------------------
extern __shared__ char smraw[];

__global__ void __launch_bounds__(NT, 2)
urmlp_kernel(const float* __restrict__ b1c,
             const float* __restrict__ eln1w, const float* __restrict__ eln1b,
             const float* __restrict__ ef2b,
             const float* __restrict__ eln2w, const float* __restrict__ eln2b,
             const float* __restrict__ ef3b,
             const float* __restrict__ ln1w,  const float* __restrict__ ln1b,
             const float* __restrict__ f2b,
             const float* __restrict__ ln2w,  const float* __restrict__ ln2b,
             const float* __restrict__ f3b,
             float* __restrict__ out)
{
    char* sm = smraw;
    const int tid  = threadIdx.x;
    const int warp = tid >> 5;
    const int lane = tid & 31;
    const int bid  = blockIdx.x;
    const int tile = bid / 9;
    const int br   = bid - tile * 9;
    const int base = tile * TE;
    const int nvalid = min(TE, E_TOT - base);
    const uint32_t sb = s2u(sm);

    // g1: W1 -> W buf
    cp_weights(sb + OFF_W, br, tid);

    // g2: x tile -> A; zero-fill invalid rows
    {
        for (int i = tid; i < TE * 16; i += NT) {       // 16 x 16B chunks per row
            const int row = i >> 4, ch = i & 15;
            const uint32_t dh = sb + OFF_A + row * RB + ch * 16;
            if (row < nvalid) {
                cpa16(dh, g_x + (size_t)(base + row) * 128 + ch * 8);
            } else {
                *(uint4*)(sm + OFF_A + row * RB + ch * 16) = make_uint4(0, 0, 0, 0);
            }
        }
        cpa_commit();
    }

    // per-branch vectors: [b1, lw1, lb1, b2, lw2, lb2, b3]
    if (tid < 128) {
        float* vec = (float*)(sm + OFF_VEC);
        const float* s0 = b1c + br * 128;
        const float* s1 = br ? ln1w + (br - 1) * 128 : eln1w;
        const float* s2 = br ? ln1b + (br - 1) * 128 : eln1b;
        const float* s3 = br ? f2b  + (br - 1) * 128 : ef2b;
        const float* s4 = br ? ln2w + (br - 1) * 128 : eln2w;
        const float* s5 = br ? ln2b + (br - 1) * 128 : eln2b;
        const float* s6 = br ? f3b  + (br - 1) * 128 : ef3b;
        vec[0 * 128 + tid] = __ldg(s0 + tid);
        vec[1 * 128 + tid] = __ldg(s1 + tid);
        vec[2 * 128 + tid] = __ldg(s2 + tid);
        vec[3 * 128 + tid] = __ldg(s3 + tid);
        vec[4 * 128 + tid] = __ldg(s4 + tid);
        vec[5 * 128 + tid] = __ldg(s5 + tid);
        vec[6 * 128 + tid] = __ldg(s6 + tid);
    }

    asm volatile("cp.async.wait_group 0;" ::: "memory");
    __syncthreads();

    float acc[2][8][4];

    // ---- stage 1 ----
    gemm128(sb, acc, warp, lane);
    __syncthreads();                    // all reads of a/w done
    cp_weights(sb + OFF_W, 9 + br, tid);   // W2, overlaps epilogue
    epilogue_ln(sm, acc, 0, warp, lane);
    asm volatile("cp.async.wait_group 0;" ::: "memory");
    __syncthreads();

    // ---- stage 2 ----
    gemm128(sb, acc, warp, lane);
    __syncthreads();
    cp_weights(sb + OFF_W, 18 + br, tid);  // W3
    epilogue_ln(sm, acc, 3, warp, lane);
    asm volatile("cp.async.wait_group 0;" ::: "memory");
    __syncthreads();

    // ---- stage 3: out = h @ fc3^T + b3 ----
    gemm128(sb, acc, warp, lane);
    {
        const int tig  = lane & 3;
        const int grp  = lane >> 2;
        const int mblk = (warp >> 1) << 5;
        const int nblk = (warp & 1) << 6;
        const float* bias = (const float*)(sm + OFF_VEC) + 6 * 128;
#pragma unroll
        for (int mi = 0; mi < 2; mi++) {
            const int r0 = mblk + grp + (mi << 4);
            const int r1 = r0 + 8;
            float* o0 = out + ((size_t)br * E_TOT + base + r0) * 128;
            float* o1 = o0 + (size_t)8 * 128;
#pragma unroll
            for (int nj = 0; nj < 8; nj++) {
                const int c = nblk + (nj << 3) + (tig << 1);
                const float b0 = bias[c], b1 = bias[c + 1];
                const float* a = acc[mi][nj];
                if (r0 < nvalid)
                    *(float2*)(o0 + c) = make_float2(a[0] + b0, a[1] + b1);
                if (r1 < nvalid)
                    *(float2*)(o1 + c) = make_float2(a[2] + b0, a[3] + b1);
            }
        }
    }
}

extern "C" void kernel_launch(void* const* d_in, const int* in_sizes, int n_in,
                              void* d_out, int out_size) {
    const float* x     = (const float*)d_in[0];
    const float* W1    = (const float*)d_in[1];
    const float* b1    = (const float*)d_in[2];
    const float* eln1w = (const float*)d_in[3];
    const float* eln1b = (const float*)d_in[4];
    const float* ef2w  = (const float*)d_in[5];
    const float* ef2b  = (const float*)d_in[6];
    const float* eln2w = (const float*)d_in[7];
    const float* eln2b = (const float*)d_in[8];
    const float* ef3w  = (const float*)d_in[9];
    const float* ef3b  = (const float*)d_in[10];
    const float* ln1w  = (const float*)d_in[11];
    const float* ln1b  = (const float*)d_in[12];
    const float* f2w   = (const float*)d_in[13];
    const float* f2b   = (const float*)d_in[14];
    const float* ln2w  = (const float*)d_in[15];
    const float* ln2b  = (const float*)d_in[16];
    const float* f3w   = (const float*)d_in[17];
    const float* f3b   = (const float*)d_in[18];
    float* out = (float*)d_out;

    cudaFuncSetAttribute(urmlp_kernel, cudaFuncAttributeMaxDynamicSharedMemorySize, SMEM_SZ);

    const int xblocks = (E_TOT * 32 + 255) / 256;
    prep_all<<<27 + xblocks, 256>>>(x, W1, ef2w, f2w, ef3w, f3w);

    const int tiles = (E_TOT + TE - 1) / TE;   // 1172
    urmlp_kernel<<<tiles * 9, NT, SMEM_SZ>>>(
        b1, eln1w, eln1b, ef2b, eln2w, eln2b, ef3b,
        ln1w, ln1b, f2b, ln2w, ln2b, f3b, out);
}